// round 4
// baseline (speedup 1.0000x reference)
#include <cuda_runtime.h>
#include <cstdint>

#define D 64
#define KNB 64
#define PAD 68     // padded row stride (floats) for smem tiles

typedef unsigned long long ull;

__device__ float g_W1t[D * D];        // g_W1t[f*64+d] = fc_w[d*128+f]
__device__ __align__(16) float g_W2t[D * PAD];  // g_W2t[f*68+d] = fc_w[d*128+64+f]

__device__ __forceinline__ ull pack2(float a, float b) {
    ull r;
    asm("mov.b64 %0, {%1, %2};" : "=l"(r) : "r"(__float_as_uint(a)), "r"(__float_as_uint(b)));
    return r;
}
__device__ __forceinline__ ull fma2(ull a, ull b, ull c) {
    ull d;
    asm("fma.rn.f32x2 %0, %1, %2, %3;" : "=l"(d) : "l"(a), "l"(b), "l"(c));
    return d;
}
__device__ __forceinline__ void unpack2(ull v, float& lo, float& hi) {
    unsigned int l, h;
    asm("mov.b64 {%0, %1}, %2;" : "=r"(l), "=r"(h) : "l"(v));
    lo = __uint_as_float(l); hi = __uint_as_float(h);
}
__device__ __forceinline__ float getc(const float4& v, int i) {
    return (i == 0) ? v.x : (i == 1) ? v.y : (i == 2) ? v.z : v.w;
}
__device__ __forceinline__ float dot4(const float4& a, const float4& b) {
    return a.x * b.x + a.y * b.y + a.z * b.z + a.w * b.w;
}

__global__ void transpose_w_kernel(const float* __restrict__ fc_w) {
    int i = blockIdx.x * 256 + threadIdx.x;
    if (i < D * 2 * D) {
        int d = i >> 7, f = i & 127;
        float v = fc_w[i];
        if (f < 64) g_W1t[f * 64 + d] = v;
        else        g_W2t[(f - 64) * PAD + d] = v;
    }
}

__global__ void __launch_bounds__(256, 3) kgat_kernel(
    const float* __restrict__ src_embs,
    const float* __restrict__ dst_embs,
    const float* __restrict__ rel_embs,
    const float* __restrict__ fc_b,
    const int*   __restrict__ mask,
    float* __restrict__ out)
{
    extern __shared__ float smem[];
    float* sW2  = smem;                  // [64 f][PAD]  (transposed W2)
    float* sdst = sW2  + D * PAD;        // [K][PAD]
    float* srel = sdst + KNB * PAD;      // [K][PAD]

    __shared__ float ssrc[D], shs[D], sg[D], sb[D];
    __shared__ float sc1[KNB], sc2[KNB], sr2[KNB];
    __shared__ float sdr[KNB], sdh[KNB], satt[KNB];
    __shared__ int   smask[KNB];
    __shared__ float s_s2;

    const int n = blockIdx.x;
    const int t = threadIdx.x;

    const float* gdst = dst_embs + (size_t)n * (KNB * D);
    const float* grel = rel_embs + (size_t)n * (KNB * D);

    // ---- prologue loads ----
    for (int i = t; i < D * PAD / 4; i += 256)
        ((float4*)sW2)[i] = ((const float4*)g_W2t)[i];
    for (int i = t; i < KNB * D / 4; i += 256) {
        int k = i >> 4, c = (i & 15) << 2;
        *(float4*)&sdst[k * PAD + c] = ((const float4*)gdst)[i];
        *(float4*)&srel[k * PAD + c] = ((const float4*)grel)[i];
    }
    if (t < D) {
        ssrc[t] = src_embs[(size_t)n * D + t];
        sb[t] = fc_b[t];
        smask[t] = mask[(size_t)n * KNB + t];
    }
    __syncthreads();

    if (t < 128) {
        // ================= GEMM warps (0-3): hd = dst @ W2^T, fused c1/c2 =================
        const int td = t & 7, tk = t >> 3;
        const int d0 = td << 3, k0 = tk << 2;
        ull acc[4][4];
#pragma unroll
        for (int j = 0; j < 4; j++)
#pragma unroll
            for (int p = 0; p < 4; p++) acc[j][p] = 0ull;

#pragma unroll 4
        for (int fb = 0; fb < D; fb += 4) {
            float4 dv[4];
#pragma unroll
            for (int j = 0; j < 4; j++)
                dv[j] = *(const float4*)&sdst[(k0 + j) * PAD + fb];
#pragma unroll
            for (int ff = 0; ff < 4; ff++) {
                const float4 w0 = *(const float4*)&sW2[(fb + ff) * PAD + d0];
                const float4 w1 = *(const float4*)&sW2[(fb + ff) * PAD + d0 + 4];
                ull wp0 = pack2(w0.x, w0.y), wp1 = pack2(w0.z, w0.w);
                ull wp2 = pack2(w1.x, w1.y), wp3 = pack2(w1.z, w1.w);
#pragma unroll
                for (int j = 0; j < 4; j++) {
                    float sv = getc(dv[j], ff);
                    ull s = pack2(sv, sv);
                    acc[j][0] = fma2(s, wp0, acc[j][0]);
                    acc[j][1] = fma2(s, wp1, acc[j][1]);
                    acc[j][2] = fma2(s, wp2, acc[j][2]);
                    acc[j][3] = fma2(s, wp3, acc[j][3]);
                }
            }
        }
        // epilogue: c1 += <hd, rel>, c2 += ||hd||^2 over this thread's 8 d-cols
        float c1p[4], c2p[4];
#pragma unroll
        for (int j = 0; j < 4; j++) {
            float4 lo, hi;
            unpack2(acc[j][0], lo.x, lo.y); unpack2(acc[j][1], lo.z, lo.w);
            unpack2(acc[j][2], hi.x, hi.y); unpack2(acc[j][3], hi.z, hi.w);
            float4 r0 = *(const float4*)&srel[(k0 + j) * PAD + d0];
            float4 r1 = *(const float4*)&srel[(k0 + j) * PAD + d0 + 4];
            c1p[j] = dot4(lo, r0) + dot4(hi, r1);
            c2p[j] = dot4(lo, lo) + dot4(hi, hi);
        }
#pragma unroll
        for (int s = 1; s < 8; s <<= 1) {
#pragma unroll
            for (int j = 0; j < 4; j++) {
                c1p[j] += __shfl_xor_sync(0xffffffffu, c1p[j], s);
                c2p[j] += __shfl_xor_sync(0xffffffffu, c2p[j], s);
            }
        }
        if (td == 0) {
#pragma unroll
            for (int j = 0; j < 4; j++) { sc1[k0 + j] = c1p[j]; sc2[k0 + j] = c2p[j]; }
        }
    } else {
        // ============ side warps (4-7): r2, hs1, g1, s2, layer-1 dr/dh ============
        const int tt = t - 128;
        // hs1 = W1 @ src + b  (W1 read from global, coalesced, L1-hit)
        if (tt < D) {
            float a0 = 0.f, a1 = 0.f, a2 = 0.f, a3 = 0.f;
#pragma unroll 4
            for (int f = 0; f < D; f += 4) {
                a0 = fmaf(ssrc[f + 0], g_W1t[(f + 0) * 64 + tt], a0);
                a1 = fmaf(ssrc[f + 1], g_W1t[(f + 1) * 64 + tt], a1);
                a2 = fmaf(ssrc[f + 2], g_W1t[(f + 2) * 64 + tt], a2);
                a3 = fmaf(ssrc[f + 3], g_W1t[(f + 3) * 64 + tt], a3);
            }
            shs[tt] = ((a0 + a1) + (a2 + a3)) + sb[tt];
        }
        asm volatile("bar.sync 1, 128;" ::: "memory");
        // g1 = W2^T @ hs1  (rows of sW2, padded -> conflict-free)
        if (tt < D) {
            const float* row = &sW2[tt * PAD];
            float a0 = 0.f, a1 = 0.f;
#pragma unroll
            for (int dd = 0; dd < D; dd += 8) {
                a0 += dot4(*(const float4*)&row[dd],     *(const float4*)&shs[dd]);
                a1 += dot4(*(const float4*)&row[dd + 4], *(const float4*)&shs[dd + 4]);
            }
            sg[tt] = a0 + a1;
        } else if (tt < 96) {
            int l = tt - 64;
            float v = shs[l] * shs[l] + shs[l + 32] * shs[l + 32];
#pragma unroll
            for (int s = 16; s; s >>= 1) v += __shfl_xor_sync(0xffffffffu, v, s);
            if (l == 0) s_s2 = v;
        }
        asm volatile("bar.sync 1, 128;" ::: "memory");
        // layer-1 dr/dh + r2  (half-row per thread)
        {
            const int k = tt >> 1, h = tt & 1;
            const int base = h * 32;
            float dr = 0.f, dh = 0.f, r2 = 0.f;
#pragma unroll
            for (int i = 0; i < 8; i++) {
                int c = base + 4 * i;
                float4 rv = *(const float4*)&srel[k * PAD + c];
                float4 dv = *(const float4*)&sdst[k * PAD + c];
                dr += dot4(*(const float4*)&shs[c], rv);
                dh += dot4(*(const float4*)&sg[c], dv);
                r2 += dot4(rv, rv);
            }
            dr += __shfl_xor_sync(0xffffffffu, dr, 1);
            dh += __shfl_xor_sync(0xffffffffu, dh, 1);
            r2 += __shfl_xor_sync(0xffffffffu, r2, 1);
            if (h == 0) { sdr[k] = dr; sdh[k] = dh; sr2[k] = r2; }
        }
    }
    __syncthreads();

    // ---- layer 1: logits + softmax (warp 0) ----
    if (t < 32) {
        float e[2];
#pragma unroll
        for (int h = 0; h < 2; h++) {
            int k = t + 32 * h;
            float num = sc1[k] + sdr[k];
            float hn2 = s_s2 + 2.0f * sdh[k] + sc2[k];
            float hn = sqrtf(fmaxf(hn2, 0.0f));
            float rn = sqrtf(sr2[k]);
            float den = fmaxf(hn, 1e-8f) * fmaxf(rn, 1e-8f);
            float ee = num / den;
            ee = (ee < 0.0f) ? 0.2f * ee : ee;
            e[h] = (smask[k] > 0) ? ee : -9e15f;
        }
        float m = fmaxf(e[0], e[1]);
#pragma unroll
        for (int s = 16; s; s >>= 1) m = fmaxf(m, __shfl_xor_sync(0xffffffffu, m, s));
        float x0 = __expf(e[0] - m), x1 = __expf(e[1] - m);
        float sum = x0 + x1;
#pragma unroll
        for (int s = 16; s; s >>= 1) sum += __shfl_xor_sync(0xffffffffu, sum, s);
        float inv = 1.0f / sum;
        satt[t] = x0 * inv; satt[t + 32] = x1 * inv;
    }
    __syncthreads();
    // ---- layer 1: agg + residual -> new src ----
    if (t < D) {
        float a0 = 0.f, a1 = 0.f, a2 = 0.f, a3 = 0.f;
#pragma unroll
        for (int k = 0; k < KNB; k += 4) {
            a0 = fmaf(satt[k + 0], sdst[(k + 0) * PAD + t], a0);
            a1 = fmaf(satt[k + 1], sdst[(k + 1) * PAD + t], a1);
            a2 = fmaf(satt[k + 2], sdst[(k + 2) * PAD + t], a2);
            a3 = fmaf(satt[k + 3], sdst[(k + 3) * PAD + t], a3);
        }
        ssrc[t] = ((a0 + a1) + (a2 + a3)) + ssrc[t];
    }
    __syncthreads();

    // ================= layer 2 =================
    if (t < D) {
        float a0 = 0.f, a1 = 0.f, a2 = 0.f, a3 = 0.f;
#pragma unroll 4
        for (int f = 0; f < D; f += 4) {
            a0 = fmaf(ssrc[f + 0], g_W1t[(f + 0) * 64 + t], a0);
            a1 = fmaf(ssrc[f + 1], g_W1t[(f + 1) * 64 + t], a1);
            a2 = fmaf(ssrc[f + 2], g_W1t[(f + 2) * 64 + t], a2);
            a3 = fmaf(ssrc[f + 3], g_W1t[(f + 3) * 64 + t], a3);
        }
        shs[t] = ((a0 + a1) + (a2 + a3)) + sb[t];
    }
    __syncthreads();
    if (t < D) {
        const float* row = &sW2[t * PAD];
        float a0 = 0.f, a1 = 0.f;
#pragma unroll
        for (int dd = 0; dd < D; dd += 8) {
            a0 += dot4(*(const float4*)&row[dd],     *(const float4*)&shs[dd]);
            a1 += dot4(*(const float4*)&row[dd + 4], *(const float4*)&shs[dd + 4]);
        }
        sg[t] = a0 + a1;
    } else if (t < 96) {
        int l = t - 64;
        float v = shs[l] * shs[l] + shs[l + 32] * shs[l + 32];
#pragma unroll
        for (int s = 16; s; s >>= 1) v += __shfl_xor_sync(0xffffffffu, v, s);
        if (l == 0) s_s2 = v;
    }
    __syncthreads();
    // dr/dh layer 2 (all 256 threads, quarter-row each)
    {
        const int k = t >> 2, q = t & 3;
        float dr = 0.f, dh = 0.f;
#pragma unroll
        for (int j = 0; j < 4; j++) {
            int c = q * 16 + 4 * j;
            dr += dot4(*(const float4*)&shs[c], *(const float4*)&srel[k * PAD + c]);
            dh += dot4(*(const float4*)&sg[c],  *(const float4*)&sdst[k * PAD + c]);
        }
        dr += __shfl_xor_sync(0xffffffffu, dr, 1);
        dh += __shfl_xor_sync(0xffffffffu, dh, 1);
        dr += __shfl_xor_sync(0xffffffffu, dr, 2);
        dh += __shfl_xor_sync(0xffffffffu, dh, 2);
        if (q == 0) { sdr[k] = dr; sdh[k] = dh; }
    }
    __syncthreads();
    if (t < 32) {
        float e[2];
#pragma unroll
        for (int h = 0; h < 2; h++) {
            int k = t + 32 * h;
            float num = sc1[k] + sdr[k];
            float hn2 = s_s2 + 2.0f * sdh[k] + sc2[k];
            float hn = sqrtf(fmaxf(hn2, 0.0f));
            float rn = sqrtf(sr2[k]);
            float den = fmaxf(hn, 1e-8f) * fmaxf(rn, 1e-8f);
            float ee = num / den;
            ee = (ee < 0.0f) ? 0.2f * ee : ee;
            e[h] = (smask[k] > 0) ? ee : -9e15f;
        }
        float m = fmaxf(e[0], e[1]);
#pragma unroll
        for (int s = 16; s; s >>= 1) m = fmaxf(m, __shfl_xor_sync(0xffffffffu, m, s));
        float x0 = __expf(e[0] - m), x1 = __expf(e[1] - m);
        float sum = x0 + x1;
#pragma unroll
        for (int s = 16; s; s >>= 1) sum += __shfl_xor_sync(0xffffffffu, sum, s);
        float inv = 1.0f / sum;
        satt[t] = x0 * inv; satt[t + 32] = x1 * inv;
    }
    __syncthreads();
    if (t < D) {
        float a0 = 0.f, a1 = 0.f, a2 = 0.f, a3 = 0.f;
#pragma unroll
        for (int k = 0; k < KNB; k += 4) {
            a0 = fmaf(satt[k + 0], sdst[(k + 0) * PAD + t], a0);
            a1 = fmaf(satt[k + 1], sdst[(k + 1) * PAD + t], a1);
            a2 = fmaf(satt[k + 2], sdst[(k + 2) * PAD + t], a2);
            a3 = fmaf(satt[k + 3], sdst[(k + 3) * PAD + t], a3);
        }
        out[(size_t)n * D + t] = ((a0 + a1) + (a2 + a3)) + ssrc[t];
    }
}

static const int SMEM_BYTES = (D * PAD + 2 * KNB * PAD) * (int)sizeof(float);  // 52224

extern "C" void kernel_launch(void* const* d_in, const int* in_sizes, int n_in,
                              void* d_out, int out_size) {
    const float* src  = (const float*)d_in[0];
    const float* dst  = (const float*)d_in[1];
    const float* rel  = (const float*)d_in[2];
    const float* fcw  = (const float*)d_in[3];
    const float* fcb  = (const float*)d_in[4];
    const int*   mask = (const int*)d_in[5];
    (void)n_in;

    int N = in_sizes[0] / D;   // 50000
    float* outp = (float*)d_out;
    (void)out_size;

    transpose_w_kernel<<<(D * 2 * D + 255) / 256, 256>>>(fcw);

    cudaFuncSetAttribute(kgat_kernel, cudaFuncAttributeMaxDynamicSharedMemorySize, SMEM_BYTES);
    kgat_kernel<<<N, 256, SMEM_BYTES>>>(src, dst, rel, fcb, mask, outp);
}